// round 1
// baseline (speedup 1.0000x reference)
#include <cuda_runtime.h>
#include <math.h>

// Problem constants
#define Bb 2
#define Ss 2048
#define DM 1024
#define Hh 16
#define DKh 64
#define MTOK (Bb*Ss)          // 4096
#define OUT_ELEMS ((size_t)Bb*Ss*DM)          // 4,194,304
#define ATTN_ELEMS ((size_t)Bb*Hh*Ss*Ss)      // 134,217,728

// Scratch (static device globals; no allocation allowed)
__device__ float g_qh[MTOK*DM];
__device__ float g_kh[MTOK*DM];
__device__ float g_vh[MTOK*DM];
__device__ float g_oh[MTOK*DM];
__device__ float g_y [MTOK*DM];

// ---------------------------------------------------------------------------
// Generic tiled SGEMM: C[M,N] = X[M,K] * W[K,N] + bias[N] (+ optional R[M,N])
// 64x64 block tile, BK=16, 256 threads, 4x4 per-thread tile.
// ---------------------------------------------------------------------------
#define TILE 64
#define BK 16

__global__ void __launch_bounds__(256)
gemm_bias_res(const float* __restrict__ X, const float* __restrict__ W,
              const float* __restrict__ bias, const float* __restrict__ R,
              float* __restrict__ C, int M, int N, int K)
{
    __shared__ float sA[BK][TILE+1];
    __shared__ float sB[BK][TILE+1];
    const int bm = blockIdx.y * TILE;
    const int bn = blockIdx.x * TILE;
    const int tid = threadIdx.x;
    const int tx = tid & 15, ty = tid >> 4;
    float acc[4][4] = {};

    for (int k0 = 0; k0 < K; k0 += BK) {
        #pragma unroll
        for (int i = 0; i < 4; ++i) {
            int e = tid + i * 256;          // 0..1023
            int m = e >> 4, kk = e & 15;
            sA[kk][m] = X[(size_t)(bm + m) * K + k0 + kk];
        }
        #pragma unroll
        for (int i = 0; i < 4; ++i) {
            int e = tid + i * 256;
            int kk = e >> 6, n = e & 63;
            sB[kk][n] = W[(size_t)(k0 + kk) * N + bn + n];
        }
        __syncthreads();
        #pragma unroll
        for (int kk = 0; kk < BK; ++kk) {
            float a[4], b[4];
            #pragma unroll
            for (int i = 0; i < 4; ++i) a[i] = sA[kk][ty * 4 + i];
            #pragma unroll
            for (int j = 0; j < 4; ++j) b[j] = sB[kk][tx * 4 + j];
            #pragma unroll
            for (int i = 0; i < 4; ++i)
                #pragma unroll
                for (int j = 0; j < 4; ++j)
                    acc[i][j] += a[i] * b[j];
        }
        __syncthreads();
    }

    #pragma unroll
    for (int i = 0; i < 4; ++i) {
        int m = bm + ty * 4 + i;
        #pragma unroll
        for (int j = 0; j < 4; ++j) {
            int n = bn + tx * 4 + j;
            float val = acc[i][j] + bias[n];
            if (R) val += R[(size_t)m * N + n];
            C[(size_t)m * N + n] = val;
        }
    }
}

// ---------------------------------------------------------------------------
// Attention scores: P[b,h,q,k] = scale * sum_d qh[b,q,h,d]*kh[b,k,h,d], masked.
// One (64q x 64k) tile per block, full Dh=64 loaded once.
// ---------------------------------------------------------------------------
__global__ void __launch_bounds__(256)
attn_scores(const float* __restrict__ qh, const float* __restrict__ kh,
            const unsigned char* __restrict__ mask, float* __restrict__ P)
{
    const int bh = blockIdx.z;               // 0..31
    const int b = bh >> 4, h = bh & 15;
    const int bq = blockIdx.y * TILE;
    const int bk = blockIdx.x * TILE;
    const int tid = threadIdx.x;
    const int tx = tid & 15, ty = tid >> 4;

    __shared__ float sQ[TILE][DKh+1];   // [q][d]
    __shared__ float sK[TILE][DKh+1];   // [k][d]

    // 4096 elements each, 16 per thread; consecutive tid -> consecutive d (coalesced)
    #pragma unroll
    for (int i = 0; i < 16; ++i) {
        int e = tid + i * 256;
        int m = e >> 6, d = e & 63;
        sQ[m][d] = qh[(size_t)(b * Ss + bq + m) * DM + h * DKh + d];
        sK[m][d] = kh[(size_t)(b * Ss + bk + m) * DM + h * DKh + d];
    }
    __syncthreads();

    float acc[4][4] = {};
    #pragma unroll 8
    for (int d = 0; d < DKh; ++d) {
        float a[4], c[4];
        #pragma unroll
        for (int i = 0; i < 4; ++i) a[i] = sQ[ty * 4 + i][d];
        #pragma unroll
        for (int j = 0; j < 4; ++j) c[j] = sK[tx * 4 + j][d];
        #pragma unroll
        for (int i = 0; i < 4; ++i)
            #pragma unroll
            for (int j = 0; j < 4; ++j)
                acc[i][j] += a[i] * c[j];
    }

    const float scale = 0.125f;  // 1/sqrt(64)
    #pragma unroll
    for (int i = 0; i < 4; ++i) {
        int q = bq + ty * 4 + i;
        #pragma unroll
        for (int j = 0; j < 4; ++j) {
            int kcol = bk + tx * 4 + j;
            float val = acc[i][j] * scale;
            if (mask[((size_t)b * Ss + q) * Ss + kcol]) val = -INFINITY;
            P[((size_t)bh * Ss + q) * Ss + kcol] = val;
        }
    }
}

// ---------------------------------------------------------------------------
// Row softmax in place (one block per row of 2048).
// ---------------------------------------------------------------------------
__global__ void __launch_bounds__(256)
softmax_rows(float* __restrict__ P)
{
    float* p = P + (size_t)blockIdx.x * Ss;
    const int tid = threadIdx.x;
    __shared__ float red[256];

    float v[8];
    float mx = -INFINITY;
    #pragma unroll
    for (int i = 0; i < 8; ++i) {
        v[i] = p[tid + i * 256];
        mx = fmaxf(mx, v[i]);
    }
    red[tid] = mx; __syncthreads();
    for (int s = 128; s > 0; s >>= 1) {
        if (tid < s) red[tid] = fmaxf(red[tid], red[tid + s]);
        __syncthreads();
    }
    mx = red[0]; __syncthreads();

    float sum = 0.f;
    #pragma unroll
    for (int i = 0; i < 8; ++i) {
        v[i] = __expf(v[i] - mx);
        sum += v[i];
    }
    red[tid] = sum; __syncthreads();
    for (int s = 128; s > 0; s >>= 1) {
        if (tid < s) red[tid] += red[tid + s];
        __syncthreads();
    }
    float inv = 1.0f / red[0];
    #pragma unroll
    for (int i = 0; i < 8; ++i) p[tid + i * 256] = v[i] * inv;
}

// ---------------------------------------------------------------------------
// PV: O[b,q,h,d] = sum_k P[b,h,q,k] * vh[b,k,h,d].  M=2048,N=64,K=2048 per (b,h)
// ---------------------------------------------------------------------------
__global__ void __launch_bounds__(256)
attn_pv(const float* __restrict__ P, const float* __restrict__ vh,
        float* __restrict__ O)
{
    const int bh = blockIdx.y;
    const int b = bh >> 4, h = bh & 15;
    const int bq = blockIdx.x * TILE;
    const int tid = threadIdx.x;
    const int tx = tid & 15, ty = tid >> 4;

    __shared__ float sP[BK][TILE+1];
    __shared__ float sV[BK][TILE+1];
    float acc[4][4] = {};

    for (int k0 = 0; k0 < Ss; k0 += BK) {
        #pragma unroll
        for (int i = 0; i < 4; ++i) {
            int e = tid + i * 256;
            int m = e >> 4, kk = e & 15;
            sP[kk][m] = P[((size_t)bh * Ss + bq + m) * Ss + k0 + kk];
        }
        #pragma unroll
        for (int i = 0; i < 4; ++i) {
            int e = tid + i * 256;
            int kk = e >> 6, n = e & 63;
            sV[kk][n] = vh[(size_t)(b * Ss + k0 + kk) * DM + h * DKh + n];
        }
        __syncthreads();
        #pragma unroll
        for (int kk = 0; kk < BK; ++kk) {
            float a[4], c[4];
            #pragma unroll
            for (int i = 0; i < 4; ++i) a[i] = sP[kk][ty * 4 + i];
            #pragma unroll
            for (int j = 0; j < 4; ++j) c[j] = sV[kk][tx * 4 + j];
            #pragma unroll
            for (int i = 0; i < 4; ++i)
                #pragma unroll
                for (int j = 0; j < 4; ++j)
                    acc[i][j] += a[i] * c[j];
        }
        __syncthreads();
    }

    #pragma unroll
    for (int i = 0; i < 4; ++i) {
        int q = bq + ty * 4 + i;
        #pragma unroll
        for (int j = 0; j < 4; ++j) {
            int d = tx * 4 + j;
            O[(size_t)(b * Ss + q) * DM + h * DKh + d] = acc[i][j];
        }
    }
}

// ---------------------------------------------------------------------------
// LayerNorm per row of 1024: out = (x-mu)*rsqrt(var+eps)*gamma + beta
// ---------------------------------------------------------------------------
__global__ void __launch_bounds__(256)
layernorm(const float* __restrict__ Xin, const float* __restrict__ gamma,
          const float* __restrict__ beta, float* __restrict__ out)
{
    const float* x = Xin + (size_t)blockIdx.x * DM;
    float* o = out + (size_t)blockIdx.x * DM;
    const int tid = threadIdx.x;
    __shared__ float r1[256], r2[256];

    float v[4], s = 0.f, sq = 0.f;
    #pragma unroll
    for (int i = 0; i < 4; ++i) {
        v[i] = x[tid + i * 256];
        s += v[i];
        sq += v[i] * v[i];
    }
    r1[tid] = s; r2[tid] = sq; __syncthreads();
    for (int st = 128; st > 0; st >>= 1) {
        if (tid < st) { r1[tid] += r1[tid + st]; r2[tid] += r2[tid + st]; }
        __syncthreads();
    }
    float mean = r1[0] * (1.0f / DM);
    float var  = r2[0] * (1.0f / DM) - mean * mean;
    float inv = rsqrtf(var + 1e-5f);
    #pragma unroll
    for (int i = 0; i < 4; ++i) {
        int c = tid + i * 256;
        o[c] = (v[i] - mean) * inv * gamma[c] + beta[c];
    }
}

// ---------------------------------------------------------------------------
extern "C" void kernel_launch(void* const* d_in, const int* in_sizes, int n_in,
                              void* d_out, int out_size)
{
    const float* q    = (const float*)d_in[0];
    const float* k    = (const float*)d_in[1];
    const float* v    = (const float*)d_in[2];
    const unsigned char* mask = (const unsigned char*)d_in[3];
    const float* Wq   = (const float*)d_in[4];
    const float* bq   = (const float*)d_in[5];
    const float* Wk   = (const float*)d_in[6];
    const float* bk   = (const float*)d_in[7];
    const float* Wv   = (const float*)d_in[8];
    const float* bv   = (const float*)d_in[9];
    const float* Wo   = (const float*)d_in[10];
    const float* bo   = (const float*)d_in[11];
    const float* ln_g = (const float*)d_in[12];
    const float* ln_b = (const float*)d_in[13];

    float* outp = (float*)d_out;
    float* attn = outp + OUT_ELEMS;    // tuple order: (out, attn)

    float *qh, *kh, *vh, *oh, *y;
    cudaGetSymbolAddress((void**)&qh, g_qh);
    cudaGetSymbolAddress((void**)&kh, g_kh);
    cudaGetSymbolAddress((void**)&vh, g_vh);
    cudaGetSymbolAddress((void**)&oh, g_oh);
    cudaGetSymbolAddress((void**)&y,  g_y);

    dim3 gProj(DM / TILE, MTOK / TILE);     // (16, 64)
    gemm_bias_res<<<gProj, 256>>>(q, Wq, bq, nullptr, qh, MTOK, DM, DM);
    gemm_bias_res<<<gProj, 256>>>(k, Wk, bk, nullptr, kh, MTOK, DM, DM);
    gemm_bias_res<<<gProj, 256>>>(v, Wv, bv, nullptr, vh, MTOK, DM, DM);

    dim3 gScores(Ss / TILE, Ss / TILE, Bb * Hh);   // (32, 32, 32)
    attn_scores<<<gScores, 256>>>(qh, kh, mask, attn);

    softmax_rows<<<Bb * Hh * Ss, 256>>>(attn);     // 65536 rows

    dim3 gPV(Ss / TILE, Bb * Hh);                  // (32, 32)
    attn_pv<<<gPV, 256>>>(attn, vh, oh);

    gemm_bias_res<<<gProj, 256>>>(oh, Wo, bo, q, y, MTOK, DM, DM);

    layernorm<<<MTOK, 256>>>(y, ln_g, ln_b, outp);
}

// round 2
// speedup vs baseline: 1.4227x; 1.4227x over previous
#include <cuda_runtime.h>
#include <math.h>

// Problem constants
#define Bb 2
#define Ss 2048
#define DM 1024
#define Hh 16
#define DKh 64
#define MTOK (Bb*Ss)                           // 4096
#define NROWS (Bb*Hh*Ss)                       // 65536 attention rows
#define NKT (Ss/128)                           // 16 k-tiles per row
#define OUT_ELEMS ((size_t)Bb*Ss*DM)           // 4,194,304
#define ATTN_ELEMS ((size_t)Bb*Hh*Ss*Ss)       // 134,217,728

// Scratch (static device globals; no allocation allowed)
__device__ float g_qh[MTOK*DM];
__device__ float g_kh[MTOK*DM];
__device__ float g_vh[MTOK*DM];
__device__ float g_oh[MTOK*DM];
__device__ float g_y [MTOK*DM];
__device__ float g_smax[NKT*NROWS];
__device__ float g_ssum[NKT*NROWS];
__device__ float g_rmax[NROWS];
__device__ float g_rinv[NROWS];

// ---------------------------------------------------------------------------
// 128x128 SGEMM, BK=16, 256 threads, 8x8 per-thread register tile.
// C[M,N] = X[M,K]*W[K,N] + bias[N] (+ optional R)
// ---------------------------------------------------------------------------
__global__ void __launch_bounds__(256)
gemm128(const float* __restrict__ X, const float* __restrict__ W,
        const float* __restrict__ bias, const float* __restrict__ R,
        float* __restrict__ C, int M, int N, int K)
{
    __shared__ float sA[16][132];
    __shared__ float sB[16][132];
    const int bm = blockIdx.y * 128;
    const int bn = blockIdx.x * 128;
    const int tid = threadIdx.x;
    const int tx = tid & 15, ty = tid >> 4;
    float acc[8][8] = {};

    for (int k0 = 0; k0 < K; k0 += 16) {
        #pragma unroll
        for (int i = 0; i < 2; ++i) {
            int e = tid + i * 256;              // 0..511
            int m = e >> 2, kg = (e & 3) * 4;
            float4 v = *(const float4*)&X[(size_t)(bm + m) * K + k0 + kg];
            sA[kg+0][m] = v.x; sA[kg+1][m] = v.y; sA[kg+2][m] = v.z; sA[kg+3][m] = v.w;
        }
        #pragma unroll
        for (int i = 0; i < 2; ++i) {
            int e = tid + i * 256;
            int kk = e >> 5, ng = (e & 31) * 4;
            *(float4*)&sB[kk][ng] = *(const float4*)&W[(size_t)(k0 + kk) * N + bn + ng];
        }
        __syncthreads();
        #pragma unroll
        for (int kk = 0; kk < 16; ++kk) {
            float a[8], b[8];
            *(float4*)&a[0] = *(float4*)&sA[kk][ty*8];
            *(float4*)&a[4] = *(float4*)&sA[kk][ty*8+4];
            *(float4*)&b[0] = *(float4*)&sB[kk][tx*8];
            *(float4*)&b[4] = *(float4*)&sB[kk][tx*8+4];
            #pragma unroll
            for (int i = 0; i < 8; ++i)
                #pragma unroll
                for (int j = 0; j < 8; ++j)
                    acc[i][j] = fmaf(a[i], b[j], acc[i][j]);
        }
        __syncthreads();
    }

    #pragma unroll
    for (int i = 0; i < 8; ++i) {
        int m = bm + ty * 8 + i;
        #pragma unroll
        for (int jg = 0; jg < 2; ++jg) {
            int n = bn + tx * 8 + jg * 4;
            float4 bsv = *(const float4*)&bias[n];
            float4 o;
            o.x = acc[i][jg*4+0] + bsv.x;
            o.y = acc[i][jg*4+1] + bsv.y;
            o.z = acc[i][jg*4+2] + bsv.z;
            o.w = acc[i][jg*4+3] + bsv.w;
            if (R) {
                float4 r = *(const float4*)&R[(size_t)m * N + n];
                o.x += r.x; o.y += r.y; o.z += r.z; o.w += r.w;
            }
            *(float4*)&C[(size_t)m * N + n] = o;
        }
    }
}

// ---------------------------------------------------------------------------
// Attention scores 128x128 tile, Dh=64. Writes scaled+masked raw scores to
// attn, plus per-(row, k-tile) max and sum-of-exp partials.
// ---------------------------------------------------------------------------
__global__ void __launch_bounds__(256)
attn_scores(const float* __restrict__ qh, const float* __restrict__ kh,
            const unsigned char* __restrict__ mask, float* __restrict__ P)
{
    const int bh = blockIdx.z;
    const int b = bh >> 4, h = bh & 15;
    const int bq = blockIdx.y * 128;
    const int bk = blockIdx.x * 128;
    const int tid = threadIdx.x;
    const int tx = tid & 15, ty = tid >> 4;

    __shared__ float sQ[16][132];
    __shared__ float sK[16][132];
    float acc[8][8] = {};

    for (int k0 = 0; k0 < DKh; k0 += 16) {
        #pragma unroll
        for (int i = 0; i < 2; ++i) {
            int e = tid + i * 256;
            int m = e >> 2, kg = (e & 3) * 4;
            float4 v = *(const float4*)&qh[(size_t)(b*Ss + bq + m) * DM + h*DKh + k0 + kg];
            sQ[kg+0][m] = v.x; sQ[kg+1][m] = v.y; sQ[kg+2][m] = v.z; sQ[kg+3][m] = v.w;
        }
        #pragma unroll
        for (int i = 0; i < 2; ++i) {
            int e = tid + i * 256;
            int n = e >> 2, kg = (e & 3) * 4;
            float4 v = *(const float4*)&kh[(size_t)(b*Ss + bk + n) * DM + h*DKh + k0 + kg];
            sK[kg+0][n] = v.x; sK[kg+1][n] = v.y; sK[kg+2][n] = v.z; sK[kg+3][n] = v.w;
        }
        __syncthreads();
        #pragma unroll
        for (int kk = 0; kk < 16; ++kk) {
            float a[8], c[8];
            *(float4*)&a[0] = *(float4*)&sQ[kk][ty*8];
            *(float4*)&a[4] = *(float4*)&sQ[kk][ty*8+4];
            *(float4*)&c[0] = *(float4*)&sK[kk][tx*8];
            *(float4*)&c[4] = *(float4*)&sK[kk][tx*8+4];
            #pragma unroll
            for (int i = 0; i < 8; ++i)
                #pragma unroll
                for (int j = 0; j < 8; ++j)
                    acc[i][j] = fmaf(a[i], c[j], acc[i][j]);
        }
        __syncthreads();
    }

    const float scale = 0.125f;
    #pragma unroll
    for (int i = 0; i < 8; ++i) {
        int q = bq + ty * 8 + i;
        // mask: 8 bytes for this thread's 8 columns
        const unsigned int* mrow = (const unsigned int*)
            &mask[((size_t)b * Ss + q) * Ss + bk + tx*8];
        unsigned int mw0 = mrow[0], mw1 = mrow[1];
        float s[8];
        #pragma unroll
        for (int j = 0; j < 8; ++j) {
            unsigned int w = (j < 4) ? mw0 : mw1;
            unsigned int byte = (w >> ((j & 3) * 8)) & 0xffu;
            s[j] = byte ? -INFINITY : acc[i][j] * scale;
        }
        // write raw scores
        float* prow = &P[((size_t)bh * Ss + q) * Ss + bk + tx*8];
        *(float4*)&prow[0] = make_float4(s[0], s[1], s[2], s[3]);
        *(float4*)&prow[4] = make_float4(s[4], s[5], s[6], s[7]);
        // per-tile row stats (reduce over 16 tx lanes; rows live in half-warps)
        float mx = s[0];
        #pragma unroll
        for (int j = 1; j < 8; ++j) mx = fmaxf(mx, s[j]);
        #pragma unroll
        for (int off = 8; off > 0; off >>= 1)
            mx = fmaxf(mx, __shfl_xor_sync(0xffffffffu, mx, off));
        float sum = 0.f;
        if (mx != -INFINITY) {
            #pragma unroll
            for (int j = 0; j < 8; ++j) sum += __expf(s[j] - mx);
        }
        #pragma unroll
        for (int off = 8; off > 0; off >>= 1)
            sum += __shfl_xor_sync(0xffffffffu, sum, off);
        if (tx == 0) {
            size_t ridx = (size_t)blockIdx.x * NROWS + (size_t)bh * Ss + q;
            g_smax[ridx] = mx;
            g_ssum[ridx] = sum;
        }
    }
}

// ---------------------------------------------------------------------------
// Combine per-tile stats into per-row (max, 1/sum).
// ---------------------------------------------------------------------------
__global__ void __launch_bounds__(256)
reduce_stats()
{
    int r = blockIdx.x * 256 + threadIdx.x;   // < NROWS
    float m = -INFINITY;
    #pragma unroll
    for (int t = 0; t < NKT; ++t) m = fmaxf(m, g_smax[(size_t)t * NROWS + r]);
    float sum = 0.f;
    #pragma unroll
    for (int t = 0; t < NKT; ++t) {
        float gm = g_smax[(size_t)t * NROWS + r];
        if (gm != -INFINITY)
            sum += g_ssum[(size_t)t * NROWS + r] * __expf(gm - m);
    }
    g_rmax[r] = m;
    g_rinv[r] = 1.0f / sum;
}

// ---------------------------------------------------------------------------
// PV with fused exp-normalize: reads raw scores, computes p = exp(s-m)*inv,
// writes p back in place (final attn output), accumulates O = p @ V.
// 128 rows x 64 cols per block, 128 threads, 8x8 per thread.
// ---------------------------------------------------------------------------
__global__ void __launch_bounds__(128)
attn_pv(float* __restrict__ P, const float* __restrict__ vh,
        float* __restrict__ O)
{
    const int bh = blockIdx.y;
    const int b = bh >> 4, h = bh & 15;
    const int bq = blockIdx.x * 128;
    const int tid = threadIdx.x;
    const int tx = tid & 7, ty = tid >> 3;   // tx: 8 col groups, ty: 16 row groups

    __shared__ float sP[16][132];
    __shared__ float sV[16][72];
    __shared__ float srm[128], sri[128];

    if (tid < 128) {
        int r = bh * Ss + bq + tid;
        srm[tid] = g_rmax[r];
        sri[tid] = g_rinv[r];
    }
    __syncthreads();

    float acc[8][8] = {};

    for (int k0 = 0; k0 < Ss; k0 += 16) {
        #pragma unroll
        for (int i = 0; i < 4; ++i) {
            int e = tid + i * 128;              // 0..511
            int m = e >> 2, kg = (e & 3) * 4;
            float* paddr = &P[((size_t)bh * Ss + bq + m) * Ss + k0 + kg];
            float4 v = *(const float4*)paddr;
            float mr = srm[m], ir = sri[m];
            v.x = __expf(v.x - mr) * ir;
            v.y = __expf(v.y - mr) * ir;
            v.z = __expf(v.z - mr) * ir;
            v.w = __expf(v.w - mr) * ir;
            *(float4*)paddr = v;                 // normalized attention out
            sP[kg+0][m] = v.x; sP[kg+1][m] = v.y; sP[kg+2][m] = v.z; sP[kg+3][m] = v.w;
        }
        #pragma unroll
        for (int i = 0; i < 2; ++i) {
            int e = tid + i * 128;              // 0..255
            int kk = e >> 4, ng = (e & 15) * 4;
            *(float4*)&sV[kk][ng] =
                *(const float4*)&vh[(size_t)(b*Ss + k0 + kk) * DM + h*DKh + ng];
        }
        __syncthreads();
        #pragma unroll
        for (int kk = 0; kk < 16; ++kk) {
            float a[8], c[8];
            *(float4*)&a[0] = *(float4*)&sP[kk][ty*8];
            *(float4*)&a[4] = *(float4*)&sP[kk][ty*8+4];
            *(float4*)&c[0] = *(float4*)&sV[kk][tx*8];
            *(float4*)&c[4] = *(float4*)&sV[kk][tx*8+4];
            #pragma unroll
            for (int i = 0; i < 8; ++i)
                #pragma unroll
                for (int j = 0; j < 8; ++j)
                    acc[i][j] = fmaf(a[i], c[j], acc[i][j]);
        }
        __syncthreads();
    }

    #pragma unroll
    for (int i = 0; i < 8; ++i) {
        int q = bq + ty * 8 + i;
        #pragma unroll
        for (int jg = 0; jg < 2; ++jg) {
            int d = tx * 8 + jg * 4;
            *(float4*)&O[(size_t)(b*Ss + q) * DM + h*DKh + d] =
                make_float4(acc[i][jg*4+0], acc[i][jg*4+1], acc[i][jg*4+2], acc[i][jg*4+3]);
        }
    }
}

// ---------------------------------------------------------------------------
// LayerNorm per row of 1024
// ---------------------------------------------------------------------------
__global__ void __launch_bounds__(256)
layernorm(const float* __restrict__ Xin, const float* __restrict__ gamma,
          const float* __restrict__ beta, float* __restrict__ out)
{
    const float* x = Xin + (size_t)blockIdx.x * DM;
    float* o = out + (size_t)blockIdx.x * DM;
    const int tid = threadIdx.x;
    __shared__ float r1[256], r2[256];

    float v[4], s = 0.f, sq = 0.f;
    #pragma unroll
    for (int i = 0; i < 4; ++i) {
        v[i] = x[tid + i * 256];
        s += v[i];
        sq += v[i] * v[i];
    }
    r1[tid] = s; r2[tid] = sq; __syncthreads();
    for (int st = 128; st > 0; st >>= 1) {
        if (tid < st) { r1[tid] += r1[tid + st]; r2[tid] += r2[tid + st]; }
        __syncthreads();
    }
    float mean = r1[0] * (1.0f / DM);
    float var  = r2[0] * (1.0f / DM) - mean * mean;
    float inv = rsqrtf(var + 1e-5f);
    #pragma unroll
    for (int i = 0; i < 4; ++i) {
        int c = tid + i * 256;
        o[c] = (v[i] - mean) * inv * gamma[c] + beta[c];
    }
}

// ---------------------------------------------------------------------------
extern "C" void kernel_launch(void* const* d_in, const int* in_sizes, int n_in,
                              void* d_out, int out_size)
{
    const float* q    = (const float*)d_in[0];
    const float* k    = (const float*)d_in[1];
    const float* v    = (const float*)d_in[2];
    const unsigned char* mask = (const unsigned char*)d_in[3];
    const float* Wq   = (const float*)d_in[4];
    const float* bq   = (const float*)d_in[5];
    const float* Wk   = (const float*)d_in[6];
    const float* bk   = (const float*)d_in[7];
    const float* Wv   = (const float*)d_in[8];
    const float* bv   = (const float*)d_in[9];
    const float* Wo   = (const float*)d_in[10];
    const float* bo   = (const float*)d_in[11];
    const float* ln_g = (const float*)d_in[12];
    const float* ln_b = (const float*)d_in[13];

    float* outp = (float*)d_out;
    float* attn = outp + OUT_ELEMS;

    float *qh, *kh, *vh, *oh, *y;
    cudaGetSymbolAddress((void**)&qh, g_qh);
    cudaGetSymbolAddress((void**)&kh, g_kh);
    cudaGetSymbolAddress((void**)&vh, g_vh);
    cudaGetSymbolAddress((void**)&oh, g_oh);
    cudaGetSymbolAddress((void**)&y,  g_y);

    dim3 gProj(DM / 128, MTOK / 128);              // (8, 32)
    gemm128<<<gProj, 256>>>(q, Wq, bq, nullptr, qh, MTOK, DM, DM);
    gemm128<<<gProj, 256>>>(k, Wk, bk, nullptr, kh, MTOK, DM, DM);
    gemm128<<<gProj, 256>>>(v, Wv, bv, nullptr, vh, MTOK, DM, DM);

    dim3 gScores(Ss / 128, Ss / 128, Bb * Hh);     // (16, 16, 32)
    attn_scores<<<gScores, 256>>>(qh, kh, mask, attn);

    reduce_stats<<<NROWS / 256, 256>>>();

    dim3 gPV(Ss / 128, Bb * Hh);                   // (16, 32)
    attn_pv<<<gPV, 128>>>(attn, vh, oh);

    gemm128<<<gProj, 256>>>(oh, Wo, bo, q, y, MTOK, DM, DM);

    layernorm<<<MTOK, 256>>>(y, ln_g, ln_b, outp);
}